// round 5
// baseline (speedup 1.0000x reference)
#include <cuda_runtime.h>

// Trilinear resize [4,128,128,128,2] f32 -> [4,192,192,192,2] f32, zoom=1.5.
// Exact 3-out-per-2-in periodicity, weights {1, 1/3, 2/3}.
// No shared memory: thread = one output x column (0..191) of a 3x3 (y,z)
// output micro-strip. Input taps are direct gmem loads (L2-resident, warp
// taps span ~180B -> well coalesced); stores are 27 perfectly coalesced
// STG.64 per thread with immediate offsets.

#define IN_D  128
#define OUT_D 192

__device__ __forceinline__ float2 lerp2(float2 a, float2 b, float wa, float wb) {
    return make_float2(fmaf(a.x, wa, b.x * wb), fmaf(a.y, wa, b.y * wb));
}

__global__ __launch_bounds__(192) void resize_direct_kernel(
    const float2* __restrict__ in,   // [4,128,128,128] voxels (C=2 packed)
    float2* __restrict__ out)        // [4,192,192,192] voxels
{
    const int blk = blockIdx.x;
    const int yk = blk & 63;
    const int zk = (blk >> 6) & 63;
    const int b  = blk >> 12;

    const int t = threadIdx.x;        // output x column 0..191

    const float c13 = 1.0f / 3.0f;
    const float c23 = 2.0f / 3.0f;

    // x-taps and weights for this output column (m = t % 3)
    const int q = t / 3;
    const int m = t - 3 * q;
    int xA, xB;
    float wA;
    if (m == 0)      { xA = 2 * q;     xB = xA;                       wA = 1.0f; }
    else if (m == 1) { xA = 2 * q;     xB = 2 * q + 1;                wA = c13;  }
    else             { xA = 2 * q + 1; xB = min(2 * q + 2, IN_D - 1); wA = c23;  }
    const float wB = 1.0f - wA;

    const float2* base = in + (size_t)b * (IN_D * IN_D * IN_D);

    // x-lerp taps + y-lerp, streaming over the 3 input z planes
    float2 yl[3][3];                  // [zi][yo]
    #pragma unroll
    for (int zi = 0; zi < 3; zi++) {
        int z = min(2 * zk + zi, IN_D - 1);
        float2 xv[3];
        #pragma unroll
        for (int yi = 0; yi < 3; yi++) {
            int y = min(2 * yk + yi, IN_D - 1);
            const float2* row = base + ((size_t)z * IN_D + y) * IN_D;
            float2 a = __ldg(row + xA);
            float2 c = __ldg(row + xB);
            xv[yi] = lerp2(a, c, wA, wB);
        }
        yl[zi][0] = xv[0];
        yl[zi][1] = lerp2(xv[0], xv[1], c13, c23);
        yl[zi][2] = lerp2(xv[1], xv[2], c23, c13);
    }

    // z-lerp + 27 coalesced stores (thread t writes column t of each row)
    size_t obase = (((size_t)b * OUT_D + 3 * zk) * OUT_D + 3 * yk) * OUT_D + t;
    #pragma unroll
    for (int yo = 0; yo < 3; yo++) {
        float2 v0 = yl[0][yo];
        float2 v1 = yl[1][yo];
        float2 v2 = yl[2][yo];
        out[obase + (size_t)(0 * OUT_D + yo) * OUT_D] = v0;
        out[obase + (size_t)(1 * OUT_D + yo) * OUT_D] = lerp2(v0, v1, c13, c23);
        out[obase + (size_t)(2 * OUT_D + yo) * OUT_D] = lerp2(v1, v2, c23, c13);
    }
}

extern "C" void kernel_launch(void* const* d_in, const int* in_sizes, int n_in,
                              void* d_out, int out_size) {
    const float2* in = (const float2*)d_in[0];
    float2* out = (float2*)d_out;

    int blocks = 4 * 64 * 64;   // (b, zk, yk) = 16384
    resize_direct_kernel<<<blocks, 192>>>(in, out);
}